// round 8
// baseline (speedup 1.0000x reference)
#include <cuda_runtime.h>
#include <cuda_bf16.h>
#include <cstdint>

#define N_LEVELS 14
#define LOG2_T   19
#define T_MASK   ((1u << LOG2_T) - 1u)
#define P1       2654435761u
#define P2       805459861u
#define NTHREADS 128
#define WIDTH    64
#define W1_STRIDE 40
#define N_MAX    1048576
#define MBITS    6
#define NBINS    (1 << (3 * MBITS))      // 262144 bins (64^3)
#define SCAN_T   1024
#define BPT      (NBINS / SCAN_T)        // 256 bins per scan thread

typedef unsigned long long ull;

__device__ int g_count[NBINS];
__device__ int g_key[N_MAX];
__device__ int g_perm[N_MAX];

__device__ __forceinline__ float tanh_fast(float x) {
    float y; asm("tanh.approx.f32 %0, %1;" : "=f"(y) : "f"(x)); return y;
}
union F4B2 { float4 f4; __nv_bfloat162 b2[4]; };

__device__ __forceinline__ unsigned morton6(unsigned v) {
    unsigned r = 0;
    #pragma unroll
    for (int b = 0; b < MBITS; b++) r |= ((v >> b) & 1u) << (3 * b);
    return r;
}

// ---- kernel A: Morton key + histogram ----
__global__ void __launch_bounds__(256)
key_kernel(const float* __restrict__ x, const float* __restrict__ bbox, int n)
{
    int i = blockIdx.x * 256 + threadIdx.x;
    if (i >= n) return;
    float lo0 = bbox[0], lo1 = bbox[1], lo2 = bbox[2];
    float hi0 = bbox[3], hi1 = bbox[4], hi2 = bbox[5];
    float xn0 = (x[i * 3 + 0] - lo0) / (hi0 - lo0);
    float xn1 = (x[i * 3 + 1] - lo1) / (hi1 - lo1);
    float xn2 = (x[i * 3 + 2] - lo2) / (hi2 - lo2);
    unsigned gx = min((unsigned)(max(xn0, 0.f) * 64.f), 63u);
    unsigned gy = min((unsigned)(max(xn1, 0.f) * 64.f), 63u);
    unsigned gz = min((unsigned)(max(xn2, 0.f) * 64.f), 63u);
    int key = (int)(morton6(gx) | (morton6(gy) << 1) | (morton6(gz) << 2));
    g_key[i] = key;
    atomicAdd(&g_count[key], 1);
}

// ---- kernel B: single-block exclusive scan over NBINS (counts -> offsets in place) ----
__global__ void __launch_bounds__(SCAN_T)
scan_kernel()
{
    __shared__ int part[SCAN_T];
    int t = threadIdx.x;
    int base = t * BPT;
    int sum = 0;
    #pragma unroll 8
    for (int k = 0; k < BPT; k++) sum += g_count[base + k];
    part[t] = sum;
    __syncthreads();
    // Hillis-Steele inclusive scan on partials
    for (int d = 1; d < SCAN_T; d <<= 1) {
        int v = (t >= d) ? part[t - d] : 0;
        __syncthreads();
        part[t] += v;
        __syncthreads();
    }
    int run = (t == 0) ? 0 : part[t - 1];   // exclusive prefix of this chunk
    #pragma unroll 8
    for (int k = 0; k < BPT; k++) {
        int c = g_count[base + k];
        g_count[base + k] = run;            // counts become offsets
        run += c;
    }
}

// ---- kernel C: scatter permutation ----
__global__ void __launch_bounds__(256)
scatter_kernel(int n)
{
    int i = blockIdx.x * 256 + threadIdx.x;
    if (i >= n) return;
    int pos = atomicAdd(&g_count[g_key[i]], 1);
    g_perm[pos] = i;
}

// ---- main kernel: R3 config + perm indirection ----
__global__ void __launch_bounds__(NTHREADS, 4)
deformnet_kernel(const float* __restrict__ x,
                 const float* __restrict__ e,
                 const float* __restrict__ tables,
                 const float* __restrict__ W1, const float* __restrict__ b1,
                 const float* __restrict__ W2, const float* __restrict__ b2,
                 const float* __restrict__ W3, const float* __restrict__ b3,
                 const float* __restrict__ bbox,
                 float* __restrict__ out, int n)
{
    __shared__ __align__(16) __nv_bfloat16 sW1h[WIDTH * W1_STRIDE];
    __shared__ __align__(16) __nv_bfloat16 sW2h[WIDTH * WIDTH];
    __shared__ __align__(16) __nv_bfloat16 sW3h[3 * WIDTH];
    __shared__ float sB1[WIDTH], sB2[WIDTH], sB3[3];
    __shared__ float sBB[6];

    for (int t = threadIdx.x; t < WIDTH * W1_STRIDE; t += NTHREADS) {
        int j = t / W1_STRIDE, i = t % W1_STRIDE;
        float v = (i < 36) ? W1[i * WIDTH + j] : 0.f;
        sW1h[t] = __float2bfloat16(v);
    }
    for (int t = threadIdx.x; t < WIDTH * WIDTH; t += NTHREADS) {
        int i = t / WIDTH, j = t % WIDTH;
        sW2h[j * WIDTH + i] = __float2bfloat16(W2[t]);
    }
    for (int t = threadIdx.x; t < WIDTH * 3; t += NTHREADS) {
        int i = t / 3, j = t % 3;
        sW3h[j * WIDTH + i] = __float2bfloat16(W3[t]);
    }
    if (threadIdx.x < WIDTH) { sB1[threadIdx.x] = b1[threadIdx.x]; sB2[threadIdx.x] = b2[threadIdx.x]; }
    if (threadIdx.x < 3) sB3[threadIdx.x] = b3[threadIdx.x];
    if (threadIdx.x < 6) sBB[threadIdx.x] = bbox[threadIdx.x];
    __syncthreads();

    int slot = blockIdx.x * NTHREADS + threadIdx.x;
    if (slot >= n) return;
    const int idx = g_perm[slot];          // spatially-sorted point id

    const float lo0 = sBB[0], lo1 = sBB[1], lo2 = sBB[2];
    const float hi0 = sBB[3], hi1 = sBB[4], hi2 = sBB[5];

    const float4* e4p = (const float4*)(e + (size_t)idx * 8);
    float4 ea = __ldg(&e4p[0]);
    float4 eb = __ldg(&e4p[1]);

    float xn0 = (x[idx * 3 + 0] - lo0) / (hi0 - lo0);
    float xn1 = (x[idx * 3 + 1] - lo1) / (hi1 - lo1);
    float xn2 = (x[idx * 3 + 2] - lo2) / (hi2 - lo2);

    const float res_tab[N_LEVELS] = {16.f, 21.f, 27.f, 36.f, 48.f, 64.f, 84.f,
                                     111.f, 147.f, 194.f, 256.f, 339.f, 447.f, 590.f};

    __nv_bfloat162 inp2[20];
    const ull* __restrict__ tabs = (const ull*)tables;

    #pragma unroll
    for (int lp = 0; lp < 7; lp++) {
        float wxs[2], wys[2], wzs[2];
        unsigned hidx[16];
        #pragma unroll
        for (int s = 0; s < 2; s++) {
            const int l = lp * 2 + s;
            const float r = res_tab[l];
            float px = xn0 * r, py = xn1 * r, pz = xn2 * r;
            float bx = floorf(px), by = floorf(py), bz = floorf(pz);
            float fx = px - bx, fy = py - by, fz = pz - bz;
            wxs[s] = fx * fx * (3.f - 2.f * fx);
            wys[s] = fy * fy * (3.f - 2.f * fy);
            wzs[s] = fz * fz * (3.f - 2.f * fz);
            unsigned ix = (unsigned)bx, iy = (unsigned)by, iz = (unsigned)bz;
            unsigned hx0 = ix,      hx1 = ix + 1u;
            unsigned hy0 = iy * P1, hy1 = (iy + 1u) * P1;
            unsigned hz0 = iz * P2, hz1 = (iz + 1u) * P2;
            const unsigned base = (unsigned)l << LOG2_T;
            hidx[s * 8 + 0] = base + ((hx0 ^ hy0 ^ hz0) & T_MASK);
            hidx[s * 8 + 1] = base + ((hx0 ^ hy0 ^ hz1) & T_MASK);
            hidx[s * 8 + 2] = base + ((hx0 ^ hy1 ^ hz0) & T_MASK);
            hidx[s * 8 + 3] = base + ((hx0 ^ hy1 ^ hz1) & T_MASK);
            hidx[s * 8 + 4] = base + ((hx1 ^ hy0 ^ hz0) & T_MASK);
            hidx[s * 8 + 5] = base + ((hx1 ^ hy0 ^ hz1) & T_MASK);
            hidx[s * 8 + 6] = base + ((hx1 ^ hy1 ^ hz0) & T_MASK);
            hidx[s * 8 + 7] = base + ((hx1 ^ hy1 ^ hz1) & T_MASK);
        }
        ull cc[16];
        #pragma unroll
        for (int q = 0; q < 16; q++) cc[q] = __ldg(&tabs[hidx[q]]);

        #pragma unroll
        for (int s = 0; s < 2; s++) {
            float wx = wxs[s], wy = wys[s], wz = wzs[s];
            float ux = 1.f - wx, uy = 1.f - wy, uz = 1.f - wz;
            float w00 = ux * uy, w01 = ux * wy, w10 = wx * uy, w11 = wx * wy;
            float cw[8] = { w00 * uz, w00 * wz, w01 * uz, w01 * wz,
                            w10 * uz, w10 * wz, w11 * uz, w11 * wz };
            float a0 = 0.f, a1 = 0.f;
            #pragma unroll
            for (int q = 0; q < 8; q++) {
                float2 c = *(float2*)&cc[s * 8 + q];
                a0 = fmaf(cw[q], c.x, a0);
                a1 = fmaf(cw[q], c.y, a1);
            }
            inp2[lp * 2 + s] = __floats2bfloat162_rn(a0, a1);
        }
    }

    inp2[14] = __floats2bfloat162_rn(ea.x, ea.y);
    inp2[15] = __floats2bfloat162_rn(ea.z, ea.w);
    inp2[16] = __floats2bfloat162_rn(eb.x, eb.y);
    inp2[17] = __floats2bfloat162_rn(eb.z, eb.w);
    inp2[18] = __floats2bfloat162_rn(0.f, 0.f);
    inp2[19] = inp2[18];

    const __nv_bfloat162 zero2 = __floats2bfloat162_rn(0.f, 0.f);

    __nv_bfloat162 h1p[32];
    float h_prev = 0.f;
    #pragma unroll
    for (int j = 0; j < WIDTH; j++) {
        const float4* row = (const float4*)&sW1h[j * W1_STRIDE];
        __nv_bfloat162 acc0 = zero2, acc1 = zero2;
        #pragma unroll
        for (int q = 0; q < 5; q++) {
            F4B2 u; u.f4 = row[q];
            acc0 = __hfma2(inp2[4 * q + 0], u.b2[0], acc0);
            acc1 = __hfma2(inp2[4 * q + 1], u.b2[1], acc1);
            acc0 = __hfma2(inp2[4 * q + 2], u.b2[2], acc0);
            acc1 = __hfma2(inp2[4 * q + 3], u.b2[3], acc1);
        }
        float2 s0 = __bfloat1622float2(acc0);
        float2 s1 = __bfloat1622float2(acc1);
        float h = tanh_fast(s0.x + s0.y + s1.x + s1.y + sB1[j]);
        if (j & 1) h1p[j >> 1] = __floats2bfloat162_rn(h_prev, h); else h_prev = h;
    }

    __nv_bfloat162 h2p[32];
    #pragma unroll
    for (int j = 0; j < WIDTH; j++) {
        const float4* row = (const float4*)&sW2h[j * WIDTH];
        __nv_bfloat162 acc0 = zero2, acc1 = zero2;
        #pragma unroll
        for (int q = 0; q < 8; q++) {
            F4B2 u; u.f4 = row[q];
            acc0 = __hfma2(h1p[4 * q + 0], u.b2[0], acc0);
            acc1 = __hfma2(h1p[4 * q + 1], u.b2[1], acc1);
            acc0 = __hfma2(h1p[4 * q + 2], u.b2[2], acc0);
            acc1 = __hfma2(h1p[4 * q + 3], u.b2[3], acc1);
        }
        float2 s0 = __bfloat1622float2(acc0);
        float2 s1 = __bfloat1622float2(acc1);
        float h = tanh_fast(s0.x + s0.y + s1.x + s1.y + sB2[j]);
        if (j & 1) h2p[j >> 1] = __floats2bfloat162_rn(h_prev, h); else h_prev = h;
    }

    float o[3];
    #pragma unroll
    for (int j = 0; j < 3; j++) {
        const float4* row = (const float4*)&sW3h[j * WIDTH];
        __nv_bfloat162 acc0 = zero2, acc1 = zero2;
        #pragma unroll
        for (int q = 0; q < 8; q++) {
            F4B2 u; u.f4 = row[q];
            acc0 = __hfma2(h2p[4 * q + 0], u.b2[0], acc0);
            acc1 = __hfma2(h2p[4 * q + 1], u.b2[1], acc1);
            acc0 = __hfma2(h2p[4 * q + 2], u.b2[2], acc0);
            acc1 = __hfma2(h2p[4 * q + 3], u.b2[3], acc1);
        }
        float2 s0 = __bfloat1622float2(acc0);
        float2 s1 = __bfloat1622float2(acc1);
        o[j] = s0.x + s0.y + s1.x + s1.y + sB3[j];
    }

    out[idx * 3 + 0] = (o[0] + xn0) * (hi0 - lo0) + lo0;
    out[idx * 3 + 1] = (o[1] + xn1) * (hi1 - lo1) + lo1;
    out[idx * 3 + 2] = (o[2] + xn2) * (hi2 - lo2) + lo2;
}

extern "C" void kernel_launch(void* const* d_in, const int* in_sizes, int n_in,
                              void* d_out, int out_size)
{
    const float* x      = (const float*)d_in[0];
    const float* e      = (const float*)d_in[1];
    const float* tables = (const float*)d_in[2];
    const float* W1     = (const float*)d_in[3];
    const float* b1     = (const float*)d_in[4];
    const float* W2     = (const float*)d_in[5];
    const float* b2     = (const float*)d_in[6];
    const float* W3     = (const float*)d_in[7];
    const float* b3     = (const float*)d_in[8];
    const float* bbox   = (const float*)d_in[9];
    float* out = (float*)d_out;

    int n = in_sizes[0] / 3;

    void* pCount = nullptr;
    cudaGetSymbolAddress(&pCount, g_count);
    cudaMemsetAsync(pCount, 0, NBINS * sizeof(int), 0);

    int g256 = (n + 255) / 256;
    key_kernel<<<g256, 256>>>(x, bbox, n);
    scan_kernel<<<1, SCAN_T>>>();
    scatter_kernel<<<g256, 256>>>(n);

    int grid = (n + NTHREADS - 1) / NTHREADS;
    deformnet_kernel<<<grid, NTHREADS>>>(x, e, tables, W1, b1, W2, b2, W3, b3, bbox, out, n);
}

// round 9
// speedup vs baseline: 2.3162x; 2.3162x over previous
#include <cuda_runtime.h>
#include <cuda_bf16.h>
#include <cstdint>

#define N_LEVELS 14
#define LOG2_T   19
#define T_MASK   ((1u << LOG2_T) - 1u)
#define P1       2654435761u
#define P2       805459861u
#define NTHREADS 128
#define WIDTH    64
#define W1_STRIDE 40
#define N_MAX    1048576
#define MBITS    6
#define NBINS    (1 << (3 * MBITS))      // 262144 bins (64^3)
#define SCAN_BLOCKS 256
#define SCAN_TPB    1024                 // SCAN_BLOCKS * SCAN_TPB == NBINS

typedef unsigned long long ull;

__device__ int g_count[NBINS];
__device__ int g_bsum[SCAN_BLOCKS];
__device__ int g_key[N_MAX];
__device__ int g_perm[N_MAX];

__device__ __forceinline__ float tanh_fast(float x) {
    float y; asm("tanh.approx.f32 %0, %1;" : "=f"(y) : "f"(x)); return y;
}
union F4B2 { float4 f4; __nv_bfloat162 b2[4]; };

__device__ __forceinline__ unsigned morton6(unsigned v) {
    unsigned r = 0;
    #pragma unroll
    for (int b = 0; b < MBITS; b++) r |= ((v >> b) & 1u) << (3 * b);
    return r;
}

// ---- kernel A: Morton key + histogram ----
__global__ void __launch_bounds__(256)
key_kernel(const float* __restrict__ x, const float* __restrict__ bbox, int n)
{
    int i = blockIdx.x * 256 + threadIdx.x;
    if (i >= n) return;
    float lo0 = bbox[0], lo1 = bbox[1], lo2 = bbox[2];
    float hi0 = bbox[3], hi1 = bbox[4], hi2 = bbox[5];
    float xn0 = (x[i * 3 + 0] - lo0) / (hi0 - lo0);
    float xn1 = (x[i * 3 + 1] - lo1) / (hi1 - lo1);
    float xn2 = (x[i * 3 + 2] - lo2) / (hi2 - lo2);
    unsigned gx = min((unsigned)(max(xn0, 0.f) * 64.f), 63u);
    unsigned gy = min((unsigned)(max(xn1, 0.f) * 64.f), 63u);
    unsigned gz = min((unsigned)(max(xn2, 0.f) * 64.f), 63u);
    int key = (int)(morton6(gx) | (morton6(gy) << 1) | (morton6(gz) << 2));
    g_key[i] = key;
    atomicAdd(&g_count[key], 1);
}

// ---- scan stage 1: per-block totals (256 blocks x 1024 bins) ----
__global__ void __launch_bounds__(SCAN_TPB)
scan1_kernel()
{
    __shared__ int red[SCAN_TPB];
    int t = threadIdx.x;
    red[t] = g_count[blockIdx.x * SCAN_TPB + t];
    __syncthreads();
    #pragma unroll
    for (int d = SCAN_TPB / 2; d > 0; d >>= 1) {
        if (t < d) red[t] += red[t + d];
        __syncthreads();
    }
    if (t == 0) g_bsum[blockIdx.x] = red[0];
}

// ---- scan stage 2: exclusive scan of 256 block sums (1 block) ----
__global__ void __launch_bounds__(SCAN_BLOCKS)
scan2_kernel()
{
    __shared__ int part[SCAN_BLOCKS];
    int t = threadIdx.x;
    int v = g_bsum[t];
    part[t] = v;
    __syncthreads();
    for (int d = 1; d < SCAN_BLOCKS; d <<= 1) {
        int u = (t >= d) ? part[t - d] : 0;
        __syncthreads();
        part[t] += u;
        __syncthreads();
    }
    g_bsum[t] = part[t] - v;   // exclusive
}

// ---- scan stage 3: block-local exclusive scan + block offset ----
__global__ void __launch_bounds__(SCAN_TPB)
scan3_kernel()
{
    __shared__ int part[SCAN_TPB];
    int t = threadIdx.x;
    int gidx = blockIdx.x * SCAN_TPB + t;
    int c = g_count[gidx];
    part[t] = c;
    __syncthreads();
    for (int d = 1; d < SCAN_TPB; d <<= 1) {
        int u = (t >= d) ? part[t - d] : 0;
        __syncthreads();
        part[t] += u;
        __syncthreads();
    }
    g_count[gidx] = g_bsum[blockIdx.x] + part[t] - c;   // exclusive offset
}

// ---- kernel C: scatter permutation ----
__global__ void __launch_bounds__(256)
scatter_kernel(int n)
{
    int i = blockIdx.x * 256 + threadIdx.x;
    if (i >= n) return;
    int pos = atomicAdd(&g_count[g_key[i]], 1);
    g_perm[pos] = i;
}

// ---- main kernel: R3 config + perm indirection (unchanged from R8, 298us) ----
__global__ void __launch_bounds__(NTHREADS, 4)
deformnet_kernel(const float* __restrict__ x,
                 const float* __restrict__ e,
                 const float* __restrict__ tables,
                 const float* __restrict__ W1, const float* __restrict__ b1,
                 const float* __restrict__ W2, const float* __restrict__ b2,
                 const float* __restrict__ W3, const float* __restrict__ b3,
                 const float* __restrict__ bbox,
                 float* __restrict__ out, int n)
{
    __shared__ __align__(16) __nv_bfloat16 sW1h[WIDTH * W1_STRIDE];
    __shared__ __align__(16) __nv_bfloat16 sW2h[WIDTH * WIDTH];
    __shared__ __align__(16) __nv_bfloat16 sW3h[3 * WIDTH];
    __shared__ float sB1[WIDTH], sB2[WIDTH], sB3[3];
    __shared__ float sBB[6];

    for (int t = threadIdx.x; t < WIDTH * W1_STRIDE; t += NTHREADS) {
        int j = t / W1_STRIDE, i = t % W1_STRIDE;
        float v = (i < 36) ? W1[i * WIDTH + j] : 0.f;
        sW1h[t] = __float2bfloat16(v);
    }
    for (int t = threadIdx.x; t < WIDTH * WIDTH; t += NTHREADS) {
        int i = t / WIDTH, j = t % WIDTH;
        sW2h[j * WIDTH + i] = __float2bfloat16(W2[t]);
    }
    for (int t = threadIdx.x; t < WIDTH * 3; t += NTHREADS) {
        int i = t / 3, j = t % 3;
        sW3h[j * WIDTH + i] = __float2bfloat16(W3[t]);
    }
    if (threadIdx.x < WIDTH) { sB1[threadIdx.x] = b1[threadIdx.x]; sB2[threadIdx.x] = b2[threadIdx.x]; }
    if (threadIdx.x < 3) sB3[threadIdx.x] = b3[threadIdx.x];
    if (threadIdx.x < 6) sBB[threadIdx.x] = bbox[threadIdx.x];
    __syncthreads();

    int slot = blockIdx.x * NTHREADS + threadIdx.x;
    if (slot >= n) return;
    const int idx = g_perm[slot];          // spatially-sorted point id

    const float lo0 = sBB[0], lo1 = sBB[1], lo2 = sBB[2];
    const float hi0 = sBB[3], hi1 = sBB[4], hi2 = sBB[5];

    const float4* e4p = (const float4*)(e + (size_t)idx * 8);
    float4 ea = __ldg(&e4p[0]);
    float4 eb = __ldg(&e4p[1]);

    float xn0 = (x[idx * 3 + 0] - lo0) / (hi0 - lo0);
    float xn1 = (x[idx * 3 + 1] - lo1) / (hi1 - lo1);
    float xn2 = (x[idx * 3 + 2] - lo2) / (hi2 - lo2);

    const float res_tab[N_LEVELS] = {16.f, 21.f, 27.f, 36.f, 48.f, 64.f, 84.f,
                                     111.f, 147.f, 194.f, 256.f, 339.f, 447.f, 590.f};

    __nv_bfloat162 inp2[20];
    const ull* __restrict__ tabs = (const ull*)tables;

    #pragma unroll
    for (int lp = 0; lp < 7; lp++) {
        float wxs[2], wys[2], wzs[2];
        unsigned hidx[16];
        #pragma unroll
        for (int s = 0; s < 2; s++) {
            const int l = lp * 2 + s;
            const float r = res_tab[l];
            float px = xn0 * r, py = xn1 * r, pz = xn2 * r;
            float bx = floorf(px), by = floorf(py), bz = floorf(pz);
            float fx = px - bx, fy = py - by, fz = pz - bz;
            wxs[s] = fx * fx * (3.f - 2.f * fx);
            wys[s] = fy * fy * (3.f - 2.f * fy);
            wzs[s] = fz * fz * (3.f - 2.f * fz);
            unsigned ix = (unsigned)bx, iy = (unsigned)by, iz = (unsigned)bz;
            unsigned hx0 = ix,      hx1 = ix + 1u;
            unsigned hy0 = iy * P1, hy1 = (iy + 1u) * P1;
            unsigned hz0 = iz * P2, hz1 = (iz + 1u) * P2;
            const unsigned base = (unsigned)l << LOG2_T;
            hidx[s * 8 + 0] = base + ((hx0 ^ hy0 ^ hz0) & T_MASK);
            hidx[s * 8 + 1] = base + ((hx0 ^ hy0 ^ hz1) & T_MASK);
            hidx[s * 8 + 2] = base + ((hx0 ^ hy1 ^ hz0) & T_MASK);
            hidx[s * 8 + 3] = base + ((hx0 ^ hy1 ^ hz1) & T_MASK);
            hidx[s * 8 + 4] = base + ((hx1 ^ hy0 ^ hz0) & T_MASK);
            hidx[s * 8 + 5] = base + ((hx1 ^ hy0 ^ hz1) & T_MASK);
            hidx[s * 8 + 6] = base + ((hx1 ^ hy1 ^ hz0) & T_MASK);
            hidx[s * 8 + 7] = base + ((hx1 ^ hy1 ^ hz1) & T_MASK);
        }
        ull cc[16];
        #pragma unroll
        for (int q = 0; q < 16; q++) cc[q] = __ldg(&tabs[hidx[q]]);

        #pragma unroll
        for (int s = 0; s < 2; s++) {
            float wx = wxs[s], wy = wys[s], wz = wzs[s];
            float ux = 1.f - wx, uy = 1.f - wy, uz = 1.f - wz;
            float w00 = ux * uy, w01 = ux * wy, w10 = wx * uy, w11 = wx * wy;
            float cw[8] = { w00 * uz, w00 * wz, w01 * uz, w01 * wz,
                            w10 * uz, w10 * wz, w11 * uz, w11 * wz };
            float a0 = 0.f, a1 = 0.f;
            #pragma unroll
            for (int q = 0; q < 8; q++) {
                float2 c = *(float2*)&cc[s * 8 + q];
                a0 = fmaf(cw[q], c.x, a0);
                a1 = fmaf(cw[q], c.y, a1);
            }
            inp2[lp * 2 + s] = __floats2bfloat162_rn(a0, a1);
        }
    }

    inp2[14] = __floats2bfloat162_rn(ea.x, ea.y);
    inp2[15] = __floats2bfloat162_rn(ea.z, ea.w);
    inp2[16] = __floats2bfloat162_rn(eb.x, eb.y);
    inp2[17] = __floats2bfloat162_rn(eb.z, eb.w);
    inp2[18] = __floats2bfloat162_rn(0.f, 0.f);
    inp2[19] = inp2[18];

    const __nv_bfloat162 zero2 = __floats2bfloat162_rn(0.f, 0.f);

    __nv_bfloat162 h1p[32];
    float h_prev = 0.f;
    #pragma unroll
    for (int j = 0; j < WIDTH; j++) {
        const float4* row = (const float4*)&sW1h[j * W1_STRIDE];
        __nv_bfloat162 acc0 = zero2, acc1 = zero2;
        #pragma unroll
        for (int q = 0; q < 5; q++) {
            F4B2 u; u.f4 = row[q];
            acc0 = __hfma2(inp2[4 * q + 0], u.b2[0], acc0);
            acc1 = __hfma2(inp2[4 * q + 1], u.b2[1], acc1);
            acc0 = __hfma2(inp2[4 * q + 2], u.b2[2], acc0);
            acc1 = __hfma2(inp2[4 * q + 3], u.b2[3], acc1);
        }
        float2 s0 = __bfloat1622float2(acc0);
        float2 s1 = __bfloat1622float2(acc1);
        float h = tanh_fast(s0.x + s0.y + s1.x + s1.y + sB1[j]);
        if (j & 1) h1p[j >> 1] = __floats2bfloat162_rn(h_prev, h); else h_prev = h;
    }

    __nv_bfloat162 h2p[32];
    #pragma unroll
    for (int j = 0; j < WIDTH; j++) {
        const float4* row = (const float4*)&sW2h[j * WIDTH];
        __nv_bfloat162 acc0 = zero2, acc1 = zero2;
        #pragma unroll
        for (int q = 0; q < 8; q++) {
            F4B2 u; u.f4 = row[q];
            acc0 = __hfma2(h1p[4 * q + 0], u.b2[0], acc0);
            acc1 = __hfma2(h1p[4 * q + 1], u.b2[1], acc1);
            acc0 = __hfma2(h1p[4 * q + 2], u.b2[2], acc0);
            acc1 = __hfma2(h1p[4 * q + 3], u.b2[3], acc1);
        }
        float2 s0 = __bfloat1622float2(acc0);
        float2 s1 = __bfloat1622float2(acc1);
        float h = tanh_fast(s0.x + s0.y + s1.x + s1.y + sB2[j]);
        if (j & 1) h2p[j >> 1] = __floats2bfloat162_rn(h_prev, h); else h_prev = h;
    }

    float o[3];
    #pragma unroll
    for (int j = 0; j < 3; j++) {
        const float4* row = (const float4*)&sW3h[j * WIDTH];
        __nv_bfloat162 acc0 = zero2, acc1 = zero2;
        #pragma unroll
        for (int q = 0; q < 8; q++) {
            F4B2 u; u.f4 = row[q];
            acc0 = __hfma2(h2p[4 * q + 0], u.b2[0], acc0);
            acc1 = __hfma2(h2p[4 * q + 1], u.b2[1], acc1);
            acc0 = __hfma2(h2p[4 * q + 2], u.b2[2], acc0);
            acc1 = __hfma2(h2p[4 * q + 3], u.b2[3], acc1);
        }
        float2 s0 = __bfloat1622float2(acc0);
        float2 s1 = __bfloat1622float2(acc1);
        o[j] = s0.x + s0.y + s1.x + s1.y + sB3[j];
    }

    out[idx * 3 + 0] = (o[0] + xn0) * (hi0 - lo0) + lo0;
    out[idx * 3 + 1] = (o[1] + xn1) * (hi1 - lo1) + lo1;
    out[idx * 3 + 2] = (o[2] + xn2) * (hi2 - lo2) + lo2;
}

extern "C" void kernel_launch(void* const* d_in, const int* in_sizes, int n_in,
                              void* d_out, int out_size)
{
    const float* x      = (const float*)d_in[0];
    const float* e      = (const float*)d_in[1];
    const float* tables = (const float*)d_in[2];
    const float* W1     = (const float*)d_in[3];
    const float* b1     = (const float*)d_in[4];
    const float* W2     = (const float*)d_in[5];
    const float* b2     = (const float*)d_in[6];
    const float* W3     = (const float*)d_in[7];
    const float* b3     = (const float*)d_in[8];
    const float* bbox   = (const float*)d_in[9];
    float* out = (float*)d_out;

    int n = in_sizes[0] / 3;

    void* pCount = nullptr;
    cudaGetSymbolAddress(&pCount, g_count);
    cudaMemsetAsync(pCount, 0, NBINS * sizeof(int), 0);

    int g256 = (n + 255) / 256;
    key_kernel<<<g256, 256>>>(x, bbox, n);
    scan1_kernel<<<SCAN_BLOCKS, SCAN_TPB>>>();
    scan2_kernel<<<1, SCAN_BLOCKS>>>();
    scan3_kernel<<<SCAN_BLOCKS, SCAN_TPB>>>();
    scatter_kernel<<<g256, 256>>>(n);

    int grid = (n + NTHREADS - 1) / NTHREADS;
    deformnet_kernel<<<grid, NTHREADS>>>(x, e, tables, W1, b1, W2, b2, W3, b3, bbox, out, n);
}

// round 10
// speedup vs baseline: 2.3164x; 1.0001x over previous
#include <cuda_runtime.h>
#include <cuda_bf16.h>
#include <cstdint>

#define N_LEVELS 14
#define LOG2_T   19
#define T_MASK   ((1u << LOG2_T) - 1u)
#define P1       2654435761u
#define P2       805459861u
#define NTHREADS 128
#define WIDTH    64
#define W1_STRIDE 40
#define N_MAX    1048576
#define MBITS    6
#define NBINS    (1 << (3 * MBITS))
#define SCAN_BLOCKS 256
#define SCAN_TPB    1024

typedef unsigned long long ull;

__device__ int   g_count[NBINS];
__device__ int   g_bsum[SCAN_BLOCKS];
__device__ int   g_key[N_MAX];
__device__ int   g_perm[N_MAX];
__device__ uint2 g_feat[9 * (size_t)N_MAX];   // SoA: feat-pair q of slot i at q*N_MAX+i
__device__ float g_xn[3 * (size_t)N_MAX];     // normalized coords per slot

__device__ __forceinline__ float tanh_fast(float x) {
    float y; asm("tanh.approx.f32 %0, %1;" : "=f"(y) : "f"(x)); return y;
}
union F4B2 { float4 f4; __nv_bfloat162 b2[4]; };
union U2B2 { uint2 u; __nv_bfloat162 b[2]; };

__device__ __forceinline__ uint32_t bf2u(float lo, float hi) {
    __nv_bfloat162 t = __floats2bfloat162_rn(lo, hi);
    return *(uint32_t*)&t;
}
__device__ __forceinline__ unsigned morton6(unsigned v) {
    unsigned r = 0;
    #pragma unroll
    for (int b = 0; b < MBITS; b++) r |= ((v >> b) & 1u) << (3 * b);
    return r;
}

// ---- sort pipeline (unchanged from R9) ----
__global__ void __launch_bounds__(256)
key_kernel(const float* __restrict__ x, const float* __restrict__ bbox, int n)
{
    int i = blockIdx.x * 256 + threadIdx.x;
    if (i >= n) return;
    float lo0 = bbox[0], lo1 = bbox[1], lo2 = bbox[2];
    float hi0 = bbox[3], hi1 = bbox[4], hi2 = bbox[5];
    float xn0 = (x[i * 3 + 0] - lo0) / (hi0 - lo0);
    float xn1 = (x[i * 3 + 1] - lo1) / (hi1 - lo1);
    float xn2 = (x[i * 3 + 2] - lo2) / (hi2 - lo2);
    unsigned gx = min((unsigned)(max(xn0, 0.f) * 64.f), 63u);
    unsigned gy = min((unsigned)(max(xn1, 0.f) * 64.f), 63u);
    unsigned gz = min((unsigned)(max(xn2, 0.f) * 64.f), 63u);
    int key = (int)(morton6(gx) | (morton6(gy) << 1) | (morton6(gz) << 2));
    g_key[i] = key;
    atomicAdd(&g_count[key], 1);
}

__global__ void __launch_bounds__(SCAN_TPB)
scan1_kernel()
{
    __shared__ int red[SCAN_TPB];
    int t = threadIdx.x;
    red[t] = g_count[blockIdx.x * SCAN_TPB + t];
    __syncthreads();
    #pragma unroll
    for (int d = SCAN_TPB / 2; d > 0; d >>= 1) {
        if (t < d) red[t] += red[t + d];
        __syncthreads();
    }
    if (t == 0) g_bsum[blockIdx.x] = red[0];
}

__global__ void __launch_bounds__(SCAN_BLOCKS)
scan2_kernel()
{
    __shared__ int part[SCAN_BLOCKS];
    int t = threadIdx.x;
    int v = g_bsum[t];
    part[t] = v;
    __syncthreads();
    for (int d = 1; d < SCAN_BLOCKS; d <<= 1) {
        int u = (t >= d) ? part[t - d] : 0;
        __syncthreads();
        part[t] += u;
        __syncthreads();
    }
    g_bsum[t] = part[t] - v;
}

__global__ void __launch_bounds__(SCAN_TPB)
scan3_kernel()
{
    __shared__ int part[SCAN_TPB];
    int t = threadIdx.x;
    int gidx = blockIdx.x * SCAN_TPB + t;
    int c = g_count[gidx];
    part[t] = c;
    __syncthreads();
    for (int d = 1; d < SCAN_TPB; d <<= 1) {
        int u = (t >= d) ? part[t - d] : 0;
        __syncthreads();
        part[t] += u;
        __syncthreads();
    }
    g_count[gidx] = g_bsum[blockIdx.x] + part[t] - c;
}

__global__ void __launch_bounds__(256)
scatter_kernel(int n)
{
    int i = blockIdx.x * 256 + threadIdx.x;
    if (i >= n) return;
    int pos = atomicAdd(&g_count[g_key[i]], 1);
    g_perm[pos] = i;
}

// ---- encode kernel: pure gather, deep batching, high occupancy ----
__global__ void __launch_bounds__(NTHREADS, 5)
encode_kernel(const float* __restrict__ x,
              const float* __restrict__ e,
              const float* __restrict__ tables,
              const float* __restrict__ bbox, int n)
{
    int slot = blockIdx.x * NTHREADS + threadIdx.x;
    if (slot >= n) return;
    const int idx = g_perm[slot];

    float lo0 = bbox[0], lo1 = bbox[1], lo2 = bbox[2];
    float hi0 = bbox[3], hi1 = bbox[4], hi2 = bbox[5];

    const float4* e4p = (const float4*)(e + (size_t)idx * 8);
    float4 ea = __ldg(&e4p[0]);
    float4 eb = __ldg(&e4p[1]);

    float xn0 = (x[idx * 3 + 0] - lo0) / (hi0 - lo0);
    float xn1 = (x[idx * 3 + 1] - lo1) / (hi1 - lo1);
    float xn2 = (x[idx * 3 + 2] - lo2) / (hi2 - lo2);
    g_xn[slot]             = xn0;
    g_xn[N_MAX + slot]     = xn1;
    g_xn[2 * N_MAX + slot] = xn2;

    const float res_tab[N_LEVELS] = {16.f, 21.f, 27.f, 36.f, 48.f, 64.f, 84.f,
                                     111.f, 147.f, 194.f, 256.f, 339.f, 447.f, 590.f};
    const ull* __restrict__ tabs = (const ull*)tables;

    #pragma unroll
    for (int lp = 0; lp < 7; lp++) {
        float wxs[2], wys[2], wzs[2];
        unsigned hidx[16];
        #pragma unroll
        for (int s = 0; s < 2; s++) {
            const int l = lp * 2 + s;
            const float r = res_tab[l];
            float px = xn0 * r, py = xn1 * r, pz = xn2 * r;
            float bx = floorf(px), by = floorf(py), bz = floorf(pz);
            float fx = px - bx, fy = py - by, fz = pz - bz;
            wxs[s] = fx * fx * (3.f - 2.f * fx);
            wys[s] = fy * fy * (3.f - 2.f * fy);
            wzs[s] = fz * fz * (3.f - 2.f * fz);
            unsigned ix = (unsigned)bx, iy = (unsigned)by, iz = (unsigned)bz;
            unsigned hx0 = ix,      hx1 = ix + 1u;
            unsigned hy0 = iy * P1, hy1 = (iy + 1u) * P1;
            unsigned hz0 = iz * P2, hz1 = (iz + 1u) * P2;
            const unsigned base = (unsigned)l << LOG2_T;
            hidx[s * 8 + 0] = base + ((hx0 ^ hy0 ^ hz0) & T_MASK);
            hidx[s * 8 + 1] = base + ((hx0 ^ hy0 ^ hz1) & T_MASK);
            hidx[s * 8 + 2] = base + ((hx0 ^ hy1 ^ hz0) & T_MASK);
            hidx[s * 8 + 3] = base + ((hx0 ^ hy1 ^ hz1) & T_MASK);
            hidx[s * 8 + 4] = base + ((hx1 ^ hy0 ^ hz0) & T_MASK);
            hidx[s * 8 + 5] = base + ((hx1 ^ hy0 ^ hz1) & T_MASK);
            hidx[s * 8 + 6] = base + ((hx1 ^ hy1 ^ hz0) & T_MASK);
            hidx[s * 8 + 7] = base + ((hx1 ^ hy1 ^ hz1) & T_MASK);
        }
        ull cc[16];
        #pragma unroll
        for (int q = 0; q < 16; q++) cc[q] = __ldg(&tabs[hidx[q]]);

        uint32_t v[2];
        #pragma unroll
        for (int s = 0; s < 2; s++) {
            float wx = wxs[s], wy = wys[s], wz = wzs[s];
            float ux = 1.f - wx, uy = 1.f - wy, uz = 1.f - wz;
            float w00 = ux * uy, w01 = ux * wy, w10 = wx * uy, w11 = wx * wy;
            float cw[8] = { w00 * uz, w00 * wz, w01 * uz, w01 * wz,
                            w10 * uz, w10 * wz, w11 * uz, w11 * wz };
            float a0 = 0.f, a1 = 0.f;
            #pragma unroll
            for (int q = 0; q < 8; q++) {
                float2 c = *(float2*)&cc[s * 8 + q];
                a0 = fmaf(cw[q], c.x, a0);
                a1 = fmaf(cw[q], c.y, a1);
            }
            v[s] = bf2u(a0, a1);
        }
        g_feat[(size_t)lp * N_MAX + slot] = make_uint2(v[0], v[1]);
    }
    g_feat[(size_t)7 * N_MAX + slot] = make_uint2(bf2u(ea.x, ea.y), bf2u(ea.z, ea.w));
    g_feat[(size_t)8 * N_MAX + slot] = make_uint2(bf2u(eb.x, eb.y), bf2u(eb.z, eb.w));
}

// ---- MLP kernel: fma-bound, high occupancy ----
__global__ void __launch_bounds__(NTHREADS, 5)
mlp_kernel(const float* __restrict__ W1, const float* __restrict__ b1,
           const float* __restrict__ W2, const float* __restrict__ b2,
           const float* __restrict__ W3, const float* __restrict__ b3,
           const float* __restrict__ bbox,
           float* __restrict__ out, int n)
{
    __shared__ __align__(16) __nv_bfloat16 sW1h[WIDTH * W1_STRIDE];
    __shared__ __align__(16) __nv_bfloat16 sW2h[WIDTH * WIDTH];
    __shared__ __align__(16) __nv_bfloat16 sW3h[3 * WIDTH];
    __shared__ float sB1[WIDTH], sB2[WIDTH], sB3[3];
    __shared__ float sBB[6];

    for (int t = threadIdx.x; t < WIDTH * W1_STRIDE; t += NTHREADS) {
        int j = t / W1_STRIDE, i = t % W1_STRIDE;
        float v = (i < 36) ? W1[i * WIDTH + j] : 0.f;
        sW1h[t] = __float2bfloat16(v);
    }
    for (int t = threadIdx.x; t < WIDTH * WIDTH; t += NTHREADS) {
        int i = t / WIDTH, j = t % WIDTH;
        sW2h[j * WIDTH + i] = __float2bfloat16(W2[t]);
    }
    for (int t = threadIdx.x; t < WIDTH * 3; t += NTHREADS) {
        int i = t / 3, j = t % 3;
        sW3h[j * WIDTH + i] = __float2bfloat16(W3[t]);
    }
    if (threadIdx.x < WIDTH) { sB1[threadIdx.x] = b1[threadIdx.x]; sB2[threadIdx.x] = b2[threadIdx.x]; }
    if (threadIdx.x < 3) sB3[threadIdx.x] = b3[threadIdx.x];
    if (threadIdx.x < 6) sBB[threadIdx.x] = bbox[threadIdx.x];
    __syncthreads();

    int slot = blockIdx.x * NTHREADS + threadIdx.x;
    if (slot >= n) return;
    const int idx = g_perm[slot];

    const float lo0 = sBB[0], lo1 = sBB[1], lo2 = sBB[2];
    const float hi0 = sBB[3], hi1 = sBB[4], hi2 = sBB[5];

    float xn0 = g_xn[slot];
    float xn1 = g_xn[N_MAX + slot];
    float xn2 = g_xn[2 * N_MAX + slot];

    __nv_bfloat162 inp2[20];
    #pragma unroll
    for (int q = 0; q < 9; q++) {
        U2B2 u; u.u = g_feat[(size_t)q * N_MAX + slot];
        inp2[2 * q + 0] = u.b[0];
        inp2[2 * q + 1] = u.b[1];
    }
    const __nv_bfloat162 zero2 = __floats2bfloat162_rn(0.f, 0.f);
    inp2[18] = zero2;
    inp2[19] = zero2;

    __nv_bfloat162 h1p[32];
    float h_prev = 0.f;
    #pragma unroll
    for (int j = 0; j < WIDTH; j++) {
        const float4* row = (const float4*)&sW1h[j * W1_STRIDE];
        __nv_bfloat162 acc0 = zero2, acc1 = zero2;
        #pragma unroll
        for (int q = 0; q < 5; q++) {
            F4B2 u; u.f4 = row[q];
            acc0 = __hfma2(inp2[4 * q + 0], u.b2[0], acc0);
            acc1 = __hfma2(inp2[4 * q + 1], u.b2[1], acc1);
            acc0 = __hfma2(inp2[4 * q + 2], u.b2[2], acc0);
            acc1 = __hfma2(inp2[4 * q + 3], u.b2[3], acc1);
        }
        float2 s0 = __bfloat1622float2(acc0);
        float2 s1 = __bfloat1622float2(acc1);
        float h = tanh_fast(s0.x + s0.y + s1.x + s1.y + sB1[j]);
        if (j & 1) h1p[j >> 1] = __floats2bfloat162_rn(h_prev, h); else h_prev = h;
    }

    __nv_bfloat162 h2p[32];
    #pragma unroll
    for (int j = 0; j < WIDTH; j++) {
        const float4* row = (const float4*)&sW2h[j * WIDTH];
        __nv_bfloat162 acc0 = zero2, acc1 = zero2;
        #pragma unroll
        for (int q = 0; q < 8; q++) {
            F4B2 u; u.f4 = row[q];
            acc0 = __hfma2(h1p[4 * q + 0], u.b2[0], acc0);
            acc1 = __hfma2(h1p[4 * q + 1], u.b2[1], acc1);
            acc0 = __hfma2(h1p[4 * q + 2], u.b2[2], acc0);
            acc1 = __hfma2(h1p[4 * q + 3], u.b2[3], acc1);
        }
        float2 s0 = __bfloat1622float2(acc0);
        float2 s1 = __bfloat1622float2(acc1);
        float h = tanh_fast(s0.x + s0.y + s1.x + s1.y + sB2[j]);
        if (j & 1) h2p[j >> 1] = __floats2bfloat162_rn(h_prev, h); else h_prev = h;
    }

    float o[3];
    #pragma unroll
    for (int j = 0; j < 3; j++) {
        const float4* row = (const float4*)&sW3h[j * WIDTH];
        __nv_bfloat162 acc0 = zero2, acc1 = zero2;
        #pragma unroll
        for (int q = 0; q < 8; q++) {
            F4B2 u; u.f4 = row[q];
            acc0 = __hfma2(h2p[4 * q + 0], u.b2[0], acc0);
            acc1 = __hfma2(h2p[4 * q + 1], u.b2[1], acc1);
            acc0 = __hfma2(h2p[4 * q + 2], u.b2[2], acc0);
            acc1 = __hfma2(h2p[4 * q + 3], u.b2[3], acc1);
        }
        float2 s0 = __bfloat1622float2(acc0);
        float2 s1 = __bfloat1622float2(acc1);
        o[j] = s0.x + s0.y + s1.x + s1.y + sB3[j];
    }

    out[idx * 3 + 0] = (o[0] + xn0) * (hi0 - lo0) + lo0;
    out[idx * 3 + 1] = (o[1] + xn1) * (hi1 - lo1) + lo1;
    out[idx * 3 + 2] = (o[2] + xn2) * (hi2 - lo2) + lo2;
}

extern "C" void kernel_launch(void* const* d_in, const int* in_sizes, int n_in,
                              void* d_out, int out_size)
{
    const float* x      = (const float*)d_in[0];
    const float* e      = (const float*)d_in[1];
    const float* tables = (const float*)d_in[2];
    const float* W1     = (const float*)d_in[3];
    const float* b1     = (const float*)d_in[4];
    const float* W2     = (const float*)d_in[5];
    const float* b2     = (const float*)d_in[6];
    const float* W3     = (const float*)d_in[7];
    const float* b3     = (const float*)d_in[8];
    const float* bbox   = (const float*)d_in[9];
    float* out = (float*)d_out;

    int n = in_sizes[0] / 3;

    void* pCount = nullptr;
    cudaGetSymbolAddress(&pCount, g_count);
    cudaMemsetAsync(pCount, 0, NBINS * sizeof(int), 0);

    int g256 = (n + 255) / 256;
    key_kernel<<<g256, 256>>>(x, bbox, n);
    scan1_kernel<<<SCAN_BLOCKS, SCAN_TPB>>>();
    scan2_kernel<<<1, SCAN_BLOCKS>>>();
    scan3_kernel<<<SCAN_BLOCKS, SCAN_TPB>>>();
    scatter_kernel<<<g256, 256>>>(n);

    int grid = (n + NTHREADS - 1) / NTHREADS;
    encode_kernel<<<grid, NTHREADS>>>(x, e, tables, bbox, n);
    mlp_kernel<<<grid, NTHREADS>>>(W1, b1, W2, b2, W3, b3, bbox, out, n);
}